// round 10
// baseline (speedup 1.0000x reference)
#include <cuda_runtime.h>
#include <math.h>

#define DM 128
#define NH 8
#define NKN 16
#define BSZ 4
#define SEQ 256
#define DK 16

// ---------------- scratch (no allocations allowed) ----------------
__device__ float g_q1[BSZ*SEQ*DM];
__device__ float g_v1[BSZ*SEQ*DM];
__device__ float g_o1[BSZ*SEQ*DM];
__device__ float g_k4[BSZ*SEQ*DM];
__device__ float g_v4[BSZ*SEQ*DM];
__device__ float g_q4[NKN*DM];
__device__ float g_o4[BSZ*NKN*SEQ*DM];

__device__ __forceinline__ float warpMax(float v){
#pragma unroll
  for(int o=16;o>0;o>>=1) v = fmaxf(v, __shfl_xor_sync(0xffffffffu, v, o));
  return v;
}
__device__ __forceinline__ float warpSum(float v){
#pragma unroll
  for(int o=16;o>0;o>>=1) v += __shfl_xor_sync(0xffffffffu, v, o);
  return v;
}
__device__ __forceinline__ float fastsqrt(float x){
  float r; asm("sqrt.approx.f32 %0, %1;" : "=f"(r) : "f"(x)); return r;
}
// Reduce acc[16] across 32 lanes with 31 shfl; result: lane l holds sum for d = l>>1.
__device__ __forceinline__ float reduce16x32(const float* acc, int lane){
  float v[8];
  {
    float s[16];
#pragma unroll
    for(int d=0;d<16;d++) s[d]=acc[d]+__shfl_xor_sync(0xffffffffu,acc[d],16);
    int hi = lane&16;
#pragma unroll
    for(int k=0;k<8;k++) v[k]= hi? s[k+8]:s[k];
  }
  {
    float s[8];
#pragma unroll
    for(int k=0;k<8;k++) s[k]=v[k]+__shfl_xor_sync(0xffffffffu,v[k],8);
    int hi = lane&8;
#pragma unroll
    for(int k=0;k<4;k++) v[k]= hi? s[k+4]:s[k];
  }
  {
    float s[4];
#pragma unroll
    for(int k=0;k<4;k++) s[k]=v[k]+__shfl_xor_sync(0xffffffffu,v[k],4);
    int hi = lane&4;
#pragma unroll
    for(int k=0;k<2;k++) v[k]= hi? s[k+2]:s[k];
  }
  {
    float s0=v[0]+__shfl_xor_sync(0xffffffffu,v[0],2);
    float s1=v[1]+__shfl_xor_sync(0xffffffffu,v[1],2);
    v[0] = (lane&2)? s1:s0;
  }
  v[0]+=__shfl_xor_sync(0xffffffffu,v[0],1);
  return v[0];
}

// ------------- fused 4-way projection: C[M,128] = A@W^T + b (tile 32x64) ---
__global__ __launch_bounds__(256) void proj4(
    const float* __restrict__ A0, const float* __restrict__ W0, const float* __restrict__ B0, float* __restrict__ C0, int M0,
    const float* __restrict__ A1, const float* __restrict__ W1, const float* __restrict__ B1, float* __restrict__ C1, int M1,
    const float* __restrict__ A2, const float* __restrict__ W2, const float* __restrict__ B2, float* __restrict__ C2, int M2,
    const float* __restrict__ A3, const float* __restrict__ W3, const float* __restrict__ B3, float* __restrict__ C3, int M3)
{
  __shared__ __align__(16) float As[16][36];
  __shared__ __align__(16) float Ws[16][68];
  const float *A,*W,*Bv; float* C; int M;
  switch(blockIdx.z){
    case 0: A=A0;W=W0;Bv=B0;C=C0;M=M0; break;
    case 1: A=A1;W=W1;Bv=B1;C=C1;M=M1; break;
    case 2: A=A2;W=W2;Bv=B2;C=C2;M=M2; break;
    default:A=A3;W=W3;Bv=B3;C=C3;M=M3; break;
  }
  int bm = blockIdx.x*32;
  if (bm >= M) return;
  int bn = blockIdx.y*64;
  int t = threadIdx.x;
  int tx = t & 15, ty = t >> 4;
  float acc[2][4];
#pragma unroll
  for(int i=0;i<2;i++)
#pragma unroll
    for(int j=0;j<4;j++) acc[i][j]=0.f;

  for(int k0=0;k0<128;k0+=16){
    {
      int e=t*2; int m=e>>4, kk=e&15;
      As[kk][m]   = (bm+m<M) ? A[(size_t)(bm+m)*128 + k0+kk]   : 0.f;
      As[kk+1][m] = (bm+m<M) ? A[(size_t)(bm+m)*128 + k0+kk+1] : 0.f;
    }
#pragma unroll
    for(int i=0;i<4;i++){
      int e=t+i*256; int m=e>>4, kk=e&15;
      Ws[kk][m] = W[(size_t)(bn+m)*128 + k0+kk];
    }
    __syncthreads();
#pragma unroll
    for(int kk=0;kk<16;kk++){
      float a0=As[kk][2*ty], a1=As[kk][2*ty+1];
      float4 b=*(const float4*)&Ws[kk][4*tx];
      acc[0][0]+=a0*b.x; acc[0][1]+=a0*b.y; acc[0][2]+=a0*b.z; acc[0][3]+=a0*b.w;
      acc[1][0]+=a1*b.x; acc[1][1]+=a1*b.y; acc[1][2]+=a1*b.z; acc[1][3]+=a1*b.w;
    }
    __syncthreads();
  }
  float4 bb = *(const float4*)&Bv[bn+4*tx];
#pragma unroll
  for(int i=0;i<2;i++){
    int m = bm + 2*ty + i;
    if (m < M){
      float4 o; o.x=acc[i][0]+bb.x; o.y=acc[i][1]+bb.y; o.z=acc[i][2]+bb.z; o.w=acc[i][3]+bb.w;
      *(float4*)&C[(size_t)m*128 + bn + 4*tx] = o;
    }
  }
}

// ---------------- block1 attention (K == Q, j<=i, no maxout) ---------------
__global__ __launch_bounds__(256) void attn1_kernel(
    const float* __restrict__ q1, const float* __restrict__ v1,
    const float* __restrict__ gamma, float* __restrict__ qs,
    float* __restrict__ o1)
{
  __shared__ float kq[16][256];
  __shared__ float vt[16][256];
  int bh = blockIdx.x;
  int rg = blockIdx.y;
  int b = bh >> 3, h = bh & 7;
  int t = threadIdx.x;
  for(int e=t; e<4096; e+=256){
    int j = e>>4, d = e&15;
    size_t src = ((size_t)(b*256+j))*128 + h*16 + d;
    kq[d][j] = q1[src];
    vt[d][j] = v1[src];
  }
  __syncthreads();
  int w = t>>5, lane = t&31;
  float g = fabsf(gamma[h]);

  for(int r=0;r<8;r++){
    int i = rg*64 + w + 8*r;
    int cq = i>>5;
    float qv[16];
#pragma unroll
    for(int d=0;d<16;d++) qv[d]=kq[d][i];

    float rawv[8], Pv[8];
    float m1 = -1e30f;
#pragma unroll
    for(int c=0;c<8;c++){
      if (c > cq) break;
      int j = 32*c + lane;
      float s = 0.f;
      if (j <= i){
#pragma unroll
        for(int d=0;d<16;d++) s += qv[d]*kq[d][j];
        s *= 0.25f;
        m1 = fmaxf(m1, s);
      }
      rawv[c] = s;
    }
    m1 = warpMax(m1);

    float run = 0.f;
#pragma unroll
    for(int c=0;c<8;c++){
      if (c > cq) break;
      int j = 32*c + lane;
      float e = (j<=i) ? __expf(rawv[c]-m1) : 0.f;
      float x = e;
#pragma unroll
      for(int o=1;o<32;o<<=1){ float y=__shfl_up_sync(0xffffffffu,x,o); if (lane>=o) x += y; }
      Pv[c] = run + x;
      run  += __shfl_sync(0xffffffffu, x, 31);
    }
    float invE = 1.f/run;
    float m2p = fmaxf(m1, 0.f);

    float fs = 0.f;
#pragma unroll
    for(int c=0;c<8;c++){
      if (c > cq) break;
      int j = 32*c + lane;
      float f = 0.f;
      if (j<=i){
        float rem1 = 1.f - Pv[c]*invE;
        float dist = fastsqrt(fmaxf(rem1*(float)(i-j), 0.f));
        float eff = fmaxf(__expf(-g*dist), 1e-5f);
        f = __expf(rawv[c]*eff - m2p);
      }
      rawv[c] = f;
      fs += f;
    }
    fs = warpSum(fs);
    float inv = 1.f/fs;

    float acc[16];
#pragma unroll
    for(int d=0;d<16;d++) acc[d]=0.f;
    size_t qbase = ((size_t)bh*256 + i)*256;
#pragma unroll
    for(int c=0;c<8;c++){
      if (c > cq) break;
      int j = 32*c + lane;
      float pf = rawv[c]*inv;
      qs[qbase + j] = pf;
#pragma unroll
      for(int d=0;d<16;d++) acc[d] += pf*vt[d][j];
    }
    for(int c=cq+1;c<8;c++) qs[qbase + 32*c + lane] = 0.f;

    float red = reduce16x32(acc, lane);
    if (!(lane&1)){
      size_t ob = ((size_t)(b*256 + i))*128 + h*16;
      o1[ob + (lane>>1)] = red;
    }
  }
}

// ---------------- block4 attention v3: 4 rows per warp-pass ----------------
// lane = 8*rr + l8. j = 32c + 8jj + l8. Each V LDS.128 has 8 distinct
// addresses (128B = 1 wavefront) and serves 4 rows; cp LDS.64 = 64B.
// 8-lane reductions: acc split-tree lands d = 2*l8 (+1) -> float2 o4 store.
// 4 rows/pass x 8 warps x 4 passes = 128 rows per block (rg selects half).
__global__ __launch_bounds__(256) void attn4_kernel(
    const float* __restrict__ q4, const float* __restrict__ k4,
    const float* __restrict__ v4, const float* __restrict__ gamma,
    float* __restrict__ ks, float* __restrict__ o4)
{
  __shared__ __align__(16) float vrow[256][20];   // K rows, then V rows
  __shared__ __align__(8)  float2 cp[256];        // (c_j, P_j)
  __shared__ float qv_sh[16];
  __shared__ float m2c_sh;
  int bid = blockIdx.x;           // (b*NKN+nk)*NH + h
  int rg = blockIdx.y;            // 0..1
  int h = bid & 7;
  int bn = bid >> 3;              // b*NKN + nk
  int b = bn >> 4, nk = bn & 15;
  int t = threadIdx.x;

  if (t < 16) qv_sh[t] = q4[nk*128 + h*16 + t];
  const float* kg = k4 + (size_t)b*256*128 + h*16;
#pragma unroll
  for(int it=0; it<4; it++){
    int e = t + it*256;
    int j = e >> 2, d4 = (e & 3)*4;
    *(float4*)&vrow[j][d4] = *(const float4*)(kg + (size_t)j*128 + d4);
  }
  __syncthreads();
  {
    float s = 0.f;
#pragma unroll
    for(int u=0;u<4;u++){
      float4 kk4 = *(const float4*)&vrow[t][4*u];
      s += qv_sh[4*u]*kk4.x + qv_sh[4*u+1]*kk4.y + qv_sh[4*u+2]*kk4.z + qv_sh[4*u+3]*kk4.w;
    }
    cp[t].x = s*0.25f;
  }
  __syncthreads();
  // all threads overwrite vrow with V; warp0 additionally does max + prefix scan
  const float* vg = v4 + (size_t)b*256*128 + h*16;
#pragma unroll
  for(int it=0; it<4; it++){
    int e = t + it*256;
    int j = e >> 2, d4 = (e & 3)*4;
    *(float4*)&vrow[j][d4] = *(const float4*)(vg + (size_t)j*128 + d4);
  }
  if (t < 32){
    float m = -1e30f;
#pragma unroll
    for(int q=0;q<8;q++) m = fmaxf(m, cp[t + 32*q].x);
    m = warpMax(m);
    float loc[8]; float run = 0.f;
#pragma unroll
    for(int c=0;c<8;c++){ loc[c] = __expf(cp[t*8+c].x - m); run += loc[c]; }
    float incl = run;
#pragma unroll
    for(int o=1;o<32;o<<=1){ float y=__shfl_up_sync(0xffffffffu,incl,o); if (t>=o) incl += y; }
    float base = incl - run;
#pragma unroll
    for(int c=0;c<8;c++){ base += loc[c]; cp[t*8+c].y = base; }
    if (t==0) m2c_sh = fmaxf(m, 0.f);
  }
  __syncthreads();

  int w = t>>5, lane = t&31;
  int rr = lane>>3, l8 = lane&7;
  float g = fabsf(gamma[h]);
  float m2p = m2c_sh;
  size_t ksbh = (((size_t)(b*8 + h))*256)*4096 + (size_t)nk*256;

  for(int p=0;p<4;p++){
    int i0 = rg*128 + 4*(w + 8*p);      // 4-row group base; i0 in [rg*128, rg*128+128)
    int i_r = i0 + rr;                  // this lane's row
    int cqg = (i0 + 2) >> 5;            // max chunk for the 4-row group
    int pidx = (i_r>0)? i_r-1 : 0;
    float invE = 1.f/cp[pidx].y;

    float sv[8][4];
    float acc[16];
    float fs=0.f, fm=0.f;
#pragma unroll
    for(int d=0;d<16;d++) acc[d]=0.f;

#pragma unroll
    for(int c=0;c<8;c++){
      if (c > cqg) break;
#pragma unroll
      for(int jj=0;jj<4;jj++){
        int j = 32*c + 8*jj + l8;
        float2 cpj = cp[j];
        float f = 0.f;
        if (j < i_r){
          float rem = 1.f - cpj.y*invE;
          float dist = fastsqrt(fmaxf(rem*(float)(i_r-j),0.f));
          float eff = fmaxf(__expf(-g*dist), 1e-5f);
          f = __expf(cpj.x*eff - m2p);
        }
        sv[c][jj]=f; fs+=f; fm=fmaxf(fm,f);
        float4 v0 = *(const float4*)&vrow[j][0];
        float4 v1 = *(const float4*)&vrow[j][4];
        float4 v2 = *(const float4*)&vrow[j][8];
        float4 v3 = *(const float4*)&vrow[j][12];
        acc[0]+=f*v0.x;  acc[1]+=f*v0.y;  acc[2]+=f*v0.z;  acc[3]+=f*v0.w;
        acc[4]+=f*v1.x;  acc[5]+=f*v1.y;  acc[6]+=f*v1.z;  acc[7]+=f*v1.w;
        acc[8]+=f*v2.x;  acc[9]+=f*v2.y;  acc[10]+=f*v2.z; acc[11]+=f*v2.w;
        acc[12]+=f*v3.x; acc[13]+=f*v3.y; acc[14]+=f*v3.z; acc[15]+=f*v3.w;
      }
    }
    // reduce fs, fm over the 8 lanes of this row
#pragma unroll
    for(int o=4;o>0;o>>=1){
      fs += __shfl_xor_sync(0xffffffffu, fs, o);
      fm  = fmaxf(fm, __shfl_xor_sync(0xffffffffu, fm, o));
    }
    float fac = (fs>0.f)? fminf(1.f/fm, 5.f/fs) : 0.f;

    float* krow = ks + ksbh + (size_t)i_r*4096;
#pragma unroll
    for(int c=0;c<8;c++){
      if (c > cqg) break;
#pragma unroll
      for(int jj=0;jj<4;jj++)
        krow[32*c + 8*jj + l8] = sv[c][jj]*fac;
    }
    for(int c=cqg+1;c<8;c++)
      *(float4*)&krow[32*c + 4*l8] = make_float4(0.f,0.f,0.f,0.f);

    // reduce acc[16] over 8 lanes (split-tree): lane l8 ends with d=2*l8,2*l8+1
    float v8[8];
    {
      float s[16];
#pragma unroll
      for(int d=0;d<16;d++) s[d]=acc[d]+__shfl_xor_sync(0xffffffffu,acc[d],4);
      int hi = l8&4;
#pragma unroll
      for(int k2=0;k2<8;k2++) v8[k2]= hi? s[k2+8]:s[k2];
    }
    float v4r[4];
    {
      float s[8];
#pragma unroll
      for(int k2=0;k2<8;k2++) s[k2]=v8[k2]+__shfl_xor_sync(0xffffffffu,v8[k2],2);
      int hi = l8&2;
#pragma unroll
      for(int k2=0;k2<4;k2++) v4r[k2]= hi? s[k2+4]:s[k2];
    }
    float2 ov;
    {
      float s0=v4r[0]+__shfl_xor_sync(0xffffffffu,v4r[0],1);
      float s1=v4r[1]+__shfl_xor_sync(0xffffffffu,v4r[1],1);
      float s2=v4r[2]+__shfl_xor_sync(0xffffffffu,v4r[2],1);
      float s3=v4r[3]+__shfl_xor_sync(0xffffffffu,v4r[3],1);
      int hi = l8&1;
      ov.x = (hi? s2:s0)*fac;
      ov.y = (hi? s3:s1)*fac;
    }
    *(float2*)&o4[((size_t)(bn*256 + i_r))*128 + h*16 + 2*l8] = ov;
  }
}

// ---- fused: t = A@Wo^T+bo+res ; p = LN(t) ; v4 = p@Wv^T+bv  (tile 16x128) --
__global__ __launch_bounds__(256) void gemm_ln_v4_k(
    const float* __restrict__ A, const float* __restrict__ Wo, const float* __restrict__ bo,
    const float* __restrict__ res, const float* __restrict__ lng, const float* __restrict__ lnb,
    const float* __restrict__ Wv, const float* __restrict__ bv, float* __restrict__ out)
{
  __shared__ __align__(16) float At[16][132];
  __shared__ __align__(16) float Ws[16][132];
  int bm = blockIdx.x*16;
  int t = threadIdx.x;
  int tx = t & 31, ty = t >> 5;
#pragma unroll
  for(int i=0;i<8;i++){ int e=t+i*256; int m=e>>7, k=e&127; At[m][k]=A[(size_t)(bm+m)*128+k]; }
  __syncthreads();

  float acc[2][4];
#pragma unroll
  for(int i=0;i<2;i++)
#pragma unroll
    for(int j=0;j<4;j++) acc[i][j]=0.f;
  for(int k0=0;k0<128;k0+=16){
#pragma unroll
    for(int i=0;i<8;i++){ int e=t+i*256; int kk=e&15, n=e>>4; Ws[kk][n]=Wo[(size_t)n*128+k0+kk]; }
    __syncthreads();
#pragma unroll
    for(int kk=0;kk<16;kk++){
      float a0=At[2*ty][k0+kk], a1=At[2*ty+1][k0+kk];
      float4 bq=*(const float4*)&Ws[kk][4*tx];
      acc[0][0]+=a0*bq.x; acc[0][1]+=a0*bq.y; acc[0][2]+=a0*bq.z; acc[0][3]+=a0*bq.w;
      acc[1][0]+=a1*bq.x; acc[1][1]+=a1*bq.y; acc[1][2]+=a1*bq.z; acc[1][3]+=a1*bq.w;
    }
    __syncthreads();
  }
  {
    float4 bb=*(const float4*)&bo[4*tx];
#pragma unroll
    for(int i=0;i<2;i++){
      int m = 2*ty+i;
      float4 rr=*(const float4*)&res[(size_t)(bm+m)*128+4*tx];
      At[m][4*tx+0]=acc[i][0]+bb.x+rr.x;
      At[m][4*tx+1]=acc[i][1]+bb.y+rr.y;
      At[m][4*tx+2]=acc[i][2]+bb.z+rr.z;
      At[m][4*tx+3]=acc[i][3]+bb.w+rr.w;
    }
  }
  __syncthreads();
#pragma unroll
  for(int rr=0; rr<2; rr++){
    int m = 2*ty + rr;
    float x[4];
#pragma unroll
    for(int u=0;u<4;u++) x[u]=At[m][tx+32*u];
    float s = warpSum(x[0]+x[1]+x[2]+x[3]);
    float mean = s*(1.f/128.f);
    float vsum = 0.f;
#pragma unroll
    for(int u=0;u<4;u++){ float d=x[u]-mean; vsum += d*d; }
    vsum = warpSum(vsum);
    float rstd = rsqrtf(vsum*(1.f/128.f)+1e-5f);
#pragma unroll
    for(int u=0;u<4;u++){
      int cix = tx+32*u;
      At[m][cix] = (x[u]-mean)*rstd*lng[cix]+lnb[cix];
    }
  }
  __syncthreads();
#pragma unroll
  for(int i=0;i<2;i++)
#pragma unroll
    for(int j=0;j<4;j++) acc[i][j]=0.f;
  for(int k0=0;k0<128;k0+=16){
#pragma unroll
    for(int i=0;i<8;i++){ int e=t+i*256; int kk=e&15, n=e>>4; Ws[kk][n]=Wv[(size_t)n*128+k0+kk]; }
    __syncthreads();
#pragma unroll
    for(int kk=0;kk<16;kk++){
      float a0=At[2*ty][k0+kk], a1=At[2*ty+1][k0+kk];
      float4 bq=*(const float4*)&Ws[kk][4*tx];
      acc[0][0]+=a0*bq.x; acc[0][1]+=a0*bq.y; acc[0][2]+=a0*bq.z; acc[0][3]+=a0*bq.w;
      acc[1][0]+=a1*bq.x; acc[1][1]+=a1*bq.y; acc[1][2]+=a1*bq.z; acc[1][3]+=a1*bq.w;
    }
    __syncthreads();
  }
  {
    float4 bb=*(const float4*)&bv[4*tx];
#pragma unroll
    for(int i=0;i<2;i++){
      int m = bm + 2*ty + i;
      float4 o; o.x=acc[i][0]+bb.x; o.y=acc[i][1]+bb.y; o.z=acc[i][2]+bb.z; o.w=acc[i][3]+bb.w;
      *(float4*)&out[(size_t)m*128 + 4*tx] = o;
    }
  }
}

// ---- fused: t = A@Wo^T+bo+know ; z = LN(t) permuted-store (tile 16x128) ---
__global__ __launch_bounds__(256) void gemm_ln_z_k(
    const float* __restrict__ A, const float* __restrict__ Wo, const float* __restrict__ bo,
    const float* __restrict__ know, const float* __restrict__ lng, const float* __restrict__ lnb,
    float* __restrict__ zout)
{
  __shared__ __align__(16) float At[16][132];
  __shared__ __align__(16) float Ws[16][132];
  int bm = blockIdx.x*16;                 // row = (b*16+nk)*256 + i
  int t = threadIdx.x;
  int tx = t & 31, ty = t >> 5;
#pragma unroll
  for(int i=0;i<8;i++){ int e=t+i*256; int m=e>>7, k=e&127; At[m][k]=A[(size_t)(bm+m)*128+k]; }
  __syncthreads();

  float acc[2][4];
#pragma unroll
  for(int i=0;i<2;i++)
#pragma unroll
    for(int j=0;j<4;j++) acc[i][j]=0.f;
  for(int k0=0;k0<128;k0+=16){
#pragma unroll
    for(int i=0;i<8;i++){ int e=t+i*256; int kk=e&15, n=e>>4; Ws[kk][n]=Wo[(size_t)n*128+k0+kk]; }
    __syncthreads();
#pragma unroll
    for(int kk=0;kk<16;kk++){
      float a0=At[2*ty][k0+kk], a1=At[2*ty+1][k0+kk];
      float4 bq=*(const float4*)&Ws[kk][4*tx];
      acc[0][0]+=a0*bq.x; acc[0][1]+=a0*bq.y; acc[0][2]+=a0*bq.z; acc[0][3]+=a0*bq.w;
      acc[1][0]+=a1*bq.x; acc[1][1]+=a1*bq.y; acc[1][2]+=a1*bq.z; acc[1][3]+=a1*bq.w;
    }
    __syncthreads();
  }
  {
    float4 bb=*(const float4*)&bo[4*tx];
#pragma unroll
    for(int i=0;i<2;i++){
      int m = 2*ty+i;
      int row = bm + m;
      int nk = (row>>8)&15;
      float4 kn=*(const float4*)&know[(size_t)nk*128+4*tx];
      At[m][4*tx+0]=acc[i][0]+bb.x+kn.x;
      At[m][4*tx+1]=acc[i][1]+bb.y+kn.y;
      At[m][4*tx+2]=acc[i][2]+bb.z+kn.z;
      At[m][4*tx+3]=acc[i][3]+bb.w+kn.w;
    }
  }
  __syncthreads();
#pragma unroll
  for(int rr=0; rr<2; rr++){
    int m = 2*ty + rr;
    int row = bm + m;
    int b = row>>12, nk=(row>>8)&15, i=row&255;
    size_t zbase = (((size_t)(b*256+i))*16 + nk)*128;
    float x[4];
#pragma unroll
    for(int u=0;u<4;u++) x[u]=At[m][tx+32*u];
    float s = warpSum(x[0]+x[1]+x[2]+x[3]);
    float mean = s*(1.f/128.f);
    float vsum = 0.f;
#pragma unroll
    for(int u=0;u<4;u++){ float d=x[u]-mean; vsum += d*d; }
    vsum = warpSum(vsum);
    float rstd = rsqrtf(vsum*(1.f/128.f)+1e-5f);
#pragma unroll
    for(int u=0;u<4;u++){
      int cix = tx+32*u;
      zout[zbase + cix] = (x[u]-mean)*rstd*lng[cix]+lnb[cix];
    }
  }
}

// ---------------- launch ----------------
extern "C" void kernel_launch(void* const* d_in, const int* in_sizes, int n_in,
                              void* d_out, int out_size)
{
  const float* q_emb   = (const float*)d_in[0];
  const float* s_emb   = (const float*)d_in[1];
  const float* b1_Wq   = (const float*)d_in[3];
  const float* b1_bq   = (const float*)d_in[4];
  const float* b1_Wv   = (const float*)d_in[5];
  const float* b1_bv   = (const float*)d_in[6];
  const float* b1_Wo   = (const float*)d_in[7];
  const float* b1_bo   = (const float*)d_in[8];
  const float* b1_ga   = (const float*)d_in[9];
  const float* b1_lng  = (const float*)d_in[10];
  const float* b1_lnb  = (const float*)d_in[11];
  const float* b4_Wq   = (const float*)d_in[12];
  const float* b4_bq   = (const float*)d_in[13];
  const float* b4_Wk   = (const float*)d_in[14];
  const float* b4_bk   = (const float*)d_in[15];
  const float* b4_Wv   = (const float*)d_in[16];
  const float* b4_bv   = (const float*)d_in[17];
  const float* b4_Wo   = (const float*)d_in[18];
  const float* b4_bo   = (const float*)d_in[19];
  const float* b4_ga   = (const float*)d_in[20];
  const float* b4_lng  = (const float*)d_in[21];
  const float* b4_lnb  = (const float*)d_in[22];
  const float* know    = (const float*)d_in[23];

  float* out  = (float*)d_out;
  float* zout = out;                 // z:        4*256*16*128 = 2097152
  float* qs   = out + 2097152;       // q_scores: 4*8*256*256  = 2097152
  float* ks   = out + 4194304;       // k_scores: 4*8*256*16*256 = 33554432

  float *p_q1,*p_v1,*p_o1,*p_k4,*p_v4,*p_q4,*p_o4;
  cudaGetSymbolAddress((void**)&p_q1, g_q1);
  cudaGetSymbolAddress((void**)&p_v1, g_v1);
  cudaGetSymbolAddress((void**)&p_o1, g_o1);
  cudaGetSymbolAddress((void**)&p_k4, g_k4);
  cudaGetSymbolAddress((void**)&p_v4, g_v4);
  cudaGetSymbolAddress((void**)&p_q4, g_q4);
  cudaGetSymbolAddress((void**)&p_o4, g_o4);

  // 1) all independent projections in one launch
  proj4<<<dim3(32,2,4),256>>>(
      q_emb, b1_Wq, b1_bq, p_q1, 1024,
      s_emb, b1_Wv, b1_bv, p_v1, 1024,
      q_emb, b4_Wk, b4_bk, p_k4, 1024,
      know,  b4_Wq, b4_bq, p_q4, 16);

  // 2) block1 attention
  attn1_kernel<<<dim3(32,4),256>>>(p_q1, p_v1, b1_ga, qs, p_o1);

  // 3) o1@Wo1 + q_emb residual -> LN -> @Wv4 -> v4 (p never materialized)
  gemm_ln_v4_k<<<64,256>>>(p_o1, b1_Wo, b1_bo, q_emb, b1_lng, b1_lnb,
                           b4_Wv, b4_bv, p_v4);

  // 4) block4 attention
  attn4_kernel<<<dim3(512,2),256>>>(p_q4, p_k4, p_v4, b4_ga, ks, p_o4);

  // 5) o4@Wo4 + know residual -> LN -> permuted z
  gemm_ln_z_k<<<1024,256>>>(p_o4, b4_Wo, b4_bo, know, b4_lng, b4_lnb, zout);
}

// round 14
// speedup vs baseline: 1.1101x; 1.1101x over previous
#include <cuda_runtime.h>
#include <math.h>

#define DM 128
#define NH 8
#define NKN 16
#define BSZ 4
#define SEQ 256
#define DK 16

// ---------------- scratch (no allocations allowed) ----------------
__device__ float g_q1[BSZ*SEQ*DM];
__device__ float g_v1[BSZ*SEQ*DM];
__device__ float g_o1[BSZ*SEQ*DM];
__device__ float g_k4[BSZ*SEQ*DM];
__device__ float g_v4[BSZ*SEQ*DM];
__device__ float g_q4[NKN*DM];
__device__ float g_o4[BSZ*NKN*SEQ*DM];

__device__ __forceinline__ float warpMax(float v){
#pragma unroll
  for(int o=16;o>0;o>>=1) v = fmaxf(v, __shfl_xor_sync(0xffffffffu, v, o));
  return v;
}
__device__ __forceinline__ float warpSum(float v){
#pragma unroll
  for(int o=16;o>0;o>>=1) v += __shfl_xor_sync(0xffffffffu, v, o);
  return v;
}
__device__ __forceinline__ float fastsqrt(float x){
  float r; asm("sqrt.approx.f32 %0, %1;" : "=f"(r) : "f"(x)); return r;
}
// Reduce acc[16] across 32 lanes with 31 shfl; result: lane l holds sum for d = l>>1.
__device__ __forceinline__ float reduce16x32(const float* acc, int lane){
  float v[8];
  {
    float s[16];
#pragma unroll
    for(int d=0;d<16;d++) s[d]=acc[d]+__shfl_xor_sync(0xffffffffu,acc[d],16);
    int hi = lane&16;
#pragma unroll
    for(int k=0;k<8;k++) v[k]= hi? s[k+8]:s[k];
  }
  {
    float s[8];
#pragma unroll
    for(int k=0;k<8;k++) s[k]=v[k]+__shfl_xor_sync(0xffffffffu,v[k],8);
    int hi = lane&8;
#pragma unroll
    for(int k=0;k<4;k++) v[k]= hi? s[k+4]:s[k];
  }
  {
    float s[4];
#pragma unroll
    for(int k=0;k<4;k++) s[k]=v[k]+__shfl_xor_sync(0xffffffffu,v[k],4);
    int hi = lane&4;
#pragma unroll
    for(int k=0;k<2;k++) v[k]= hi? s[k+2]:s[k];
  }
  {
    float s0=v[0]+__shfl_xor_sync(0xffffffffu,v[0],2);
    float s1=v[1]+__shfl_xor_sync(0xffffffffu,v[1],2);
    v[0] = (lane&2)? s1:s0;
  }
  v[0]+=__shfl_xor_sync(0xffffffffu,v[0],1);
  return v[0];
}

// ------------- fused 4-way projection: C[M,128] = A@W^T + b (tile 32x64) ---
__global__ __launch_bounds__(256) void proj4(
    const float* __restrict__ A0, const float* __restrict__ W0, const float* __restrict__ B0, float* __restrict__ C0, int M0,
    const float* __restrict__ A1, const float* __restrict__ W1, const float* __restrict__ B1, float* __restrict__ C1, int M1,
    const float* __restrict__ A2, const float* __restrict__ W2, const float* __restrict__ B2, float* __restrict__ C2, int M2,
    const float* __restrict__ A3, const float* __restrict__ W3, const float* __restrict__ B3, float* __restrict__ C3, int M3)
{
  __shared__ __align__(16) float As[16][36];
  __shared__ __align__(16) float Ws[16][68];
  const float *A,*W,*Bv; float* C; int M;
  switch(blockIdx.z){
    case 0: A=A0;W=W0;Bv=B0;C=C0;M=M0; break;
    case 1: A=A1;W=W1;Bv=B1;C=C1;M=M1; break;
    case 2: A=A2;W=W2;Bv=B2;C=C2;M=M2; break;
    default:A=A3;W=W3;Bv=B3;C=C3;M=M3; break;
  }
  int bm = blockIdx.x*32;
  if (bm >= M) return;
  int bn = blockIdx.y*64;
  int t = threadIdx.x;
  int tx = t & 15, ty = t >> 4;
  float acc[2][4];
#pragma unroll
  for(int i=0;i<2;i++)
#pragma unroll
    for(int j=0;j<4;j++) acc[i][j]=0.f;

  for(int k0=0;k0<128;k0+=16){
    {
      int e=t*2; int m=e>>4, kk=e&15;
      As[kk][m]   = (bm+m<M) ? A[(size_t)(bm+m)*128 + k0+kk]   : 0.f;
      As[kk+1][m] = (bm+m<M) ? A[(size_t)(bm+m)*128 + k0+kk+1] : 0.f;
    }
#pragma unroll
    for(int i=0;i<4;i++){
      int e=t+i*256; int m=e>>4, kk=e&15;
      Ws[kk][m] = W[(size_t)(bn+m)*128 + k0+kk];
    }
    __syncthreads();
#pragma unroll
    for(int kk=0;kk<16;kk++){
      float a0=As[kk][2*ty], a1=As[kk][2*ty+1];
      float4 b=*(const float4*)&Ws[kk][4*tx];
      acc[0][0]+=a0*b.x; acc[0][1]+=a0*b.y; acc[0][2]+=a0*b.z; acc[0][3]+=a0*b.w;
      acc[1][0]+=a1*b.x; acc[1][1]+=a1*b.y; acc[1][2]+=a1*b.z; acc[1][3]+=a1*b.w;
    }
    __syncthreads();
  }
  float4 bb = *(const float4*)&Bv[bn+4*tx];
#pragma unroll
  for(int i=0;i<2;i++){
    int m = bm + 2*ty + i;
    if (m < M){
      float4 o; o.x=acc[i][0]+bb.x; o.y=acc[i][1]+bb.y; o.z=acc[i][2]+bb.z; o.w=acc[i][3]+bb.w;
      *(float4*)&C[(size_t)m*128 + bn + 4*tx] = o;
    }
  }
}

// ---------------- block1 attention (K == Q, j<=i, no maxout) ---------------
__global__ __launch_bounds__(256) void attn1_kernel(
    const float* __restrict__ q1, const float* __restrict__ v1,
    const float* __restrict__ gamma, float* __restrict__ qs,
    float* __restrict__ o1)
{
  __shared__ float kq[16][256];
  __shared__ float vt[16][256];
  int bh = blockIdx.x;
  int rg = blockIdx.y;
  int b = bh >> 3, h = bh & 7;
  int t = threadIdx.x;
  for(int e=t; e<4096; e+=256){
    int j = e>>4, d = e&15;
    size_t src = ((size_t)(b*256+j))*128 + h*16 + d;
    kq[d][j] = q1[src];
    vt[d][j] = v1[src];
  }
  __syncthreads();
  int w = t>>5, lane = t&31;
  float g = fabsf(gamma[h]);

  for(int r=0;r<8;r++){
    int i = rg*64 + w + 8*r;
    int cq = i>>5;
    float qv[16];
#pragma unroll
    for(int d=0;d<16;d++) qv[d]=kq[d][i];

    float rawv[8], Pv[8];
    float m1 = -1e30f;
#pragma unroll
    for(int c=0;c<8;c++){
      if (c > cq) break;
      int j = 32*c + lane;
      float s = 0.f;
      if (j <= i){
#pragma unroll
        for(int d=0;d<16;d++) s += qv[d]*kq[d][j];
        s *= 0.25f;
        m1 = fmaxf(m1, s);
      }
      rawv[c] = s;
    }
    m1 = warpMax(m1);

    float run = 0.f;
#pragma unroll
    for(int c=0;c<8;c++){
      if (c > cq) break;
      int j = 32*c + lane;
      float e = (j<=i) ? __expf(rawv[c]-m1) : 0.f;
      float x = e;
#pragma unroll
      for(int o=1;o<32;o<<=1){ float y=__shfl_up_sync(0xffffffffu,x,o); if (lane>=o) x += y; }
      Pv[c] = run + x;
      run  += __shfl_sync(0xffffffffu, x, 31);
    }
    float invE = 1.f/run;
    float m2p = fmaxf(m1, 0.f);

    float fs = 0.f;
#pragma unroll
    for(int c=0;c<8;c++){
      if (c > cq) break;
      int j = 32*c + lane;
      float f = 0.f;
      if (j<=i){
        float rem1 = 1.f - Pv[c]*invE;
        float dist = fastsqrt(fmaxf(rem1*(float)(i-j), 0.f));
        float eff = fmaxf(__expf(-g*dist), 1e-5f);
        f = __expf(rawv[c]*eff - m2p);
      }
      rawv[c] = f;
      fs += f;
    }
    fs = warpSum(fs);
    float inv = 1.f/fs;

    float acc[16];
#pragma unroll
    for(int d=0;d<16;d++) acc[d]=0.f;
    size_t qbase = ((size_t)bh*256 + i)*256;
#pragma unroll
    for(int c=0;c<8;c++){
      if (c > cq) break;
      int j = 32*c + lane;
      float pf = rawv[c]*inv;
      qs[qbase + j] = pf;
#pragma unroll
      for(int d=0;d<16;d++) acc[d] += pf*vt[d][j];
    }
    for(int c=cq+1;c<8;c++) qs[qbase + 32*c + lane] = 0.f;

    float red = reduce16x32(acc, lane);
    if (!(lane&1)){
      size_t ob = ((size_t)(b*256 + i))*128 + h*16;
      o1[ob + (lane>>1)] = red;
    }
  }
}

// ---------------- block4 attention v2.5: 2 rows per warp-pass --------------
// (reverted to the measured-best 2-row config: 64 regs, 4 blocks/SM)
__global__ __launch_bounds__(256) void attn4_kernel(
    const float* __restrict__ q4, const float* __restrict__ k4,
    const float* __restrict__ v4, const float* __restrict__ gamma,
    float* __restrict__ ks, float* __restrict__ o4)
{
  __shared__ __align__(16) float vrow[256][20];   // K rows, then V rows
  __shared__ __align__(8)  float2 cp[256];        // (c_j, P_j)
  __shared__ float qv_sh[16];
  __shared__ float m2c_sh;
  int bid = blockIdx.x;           // (b*NKN+nk)*NH + h
  int rg = blockIdx.y;            // 0..1
  int h = bid & 7;
  int bn = bid >> 3;              // b*NKN + nk
  int b = bn >> 4, nk = bn & 15;
  int t = threadIdx.x;

  if (t < 16) qv_sh[t] = q4[nk*128 + h*16 + t];
  const float* kg = k4 + (size_t)b*256*128 + h*16;
#pragma unroll
  for(int it=0; it<4; it++){
    int e = t + it*256;
    int j = e >> 2, d4 = (e & 3)*4;
    *(float4*)&vrow[j][d4] = *(const float4*)(kg + (size_t)j*128 + d4);
  }
  __syncthreads();
  {
    float s = 0.f;
#pragma unroll
    for(int u=0;u<4;u++){
      float4 kk4 = *(const float4*)&vrow[t][4*u];
      s += qv_sh[4*u]*kk4.x + qv_sh[4*u+1]*kk4.y + qv_sh[4*u+2]*kk4.z + qv_sh[4*u+3]*kk4.w;
    }
    cp[t].x = s*0.25f;
  }
  __syncthreads();
  // all threads overwrite vrow with V; warp0 additionally does max + prefix scan
  const float* vg = v4 + (size_t)b*256*128 + h*16;
#pragma unroll
  for(int it=0; it<4; it++){
    int e = t + it*256;
    int j = e >> 2, d4 = (e & 3)*4;
    *(float4*)&vrow[j][d4] = *(const float4*)(vg + (size_t)j*128 + d4);
  }
  if (t < 32){
    float m = -1e30f;
#pragma unroll
    for(int q=0;q<8;q++) m = fmaxf(m, cp[t + 32*q].x);
    m = warpMax(m);
    float loc[8]; float run = 0.f;
#pragma unroll
    for(int c=0;c<8;c++){ loc[c] = __expf(cp[t*8+c].x - m); run += loc[c]; }
    float incl = run;
#pragma unroll
    for(int o=1;o<32;o<<=1){ float y=__shfl_up_sync(0xffffffffu,incl,o); if (t>=o) incl += y; }
    float base = incl - run;
#pragma unroll
    for(int c=0;c<8;c++){ base += loc[c]; cp[t*8+c].y = base; }
    if (t==0) m2c_sh = fmaxf(m, 0.f);
  }
  __syncthreads();

  int w = t>>5, lane = t&31;
  int rr = lane>>4, l16 = lane&15;
  float g = fabsf(gamma[h]);
  float m2p = m2c_sh;
  size_t ksbh = (((size_t)(b*8 + h))*256)*4096 + (size_t)nk*256;

  for(int p=0;p<8;p++){
    int i0 = rg*128 + 2*(w + 8*p);
    int i_r = i0 + rr;                 // this half-warp's row
    int cqg = i0 >> 5;                 // max needed chunk for the pair
    int pidx = (i_r>0)? i_r-1 : 0;
    float invE = 1.f/cp[pidx].y;

    float sv[8][2];
    float acc[16];
    float fs=0.f, fm=0.f;
#pragma unroll
    for(int d=0;d<16;d++) acc[d]=0.f;

#pragma unroll
    for(int c=0;c<8;c++){
      if (c > cqg) break;
#pragma unroll
      for(int jj=0;jj<2;jj++){
        int j = 32*c + 16*jj + l16;
        float2 cpj = cp[j];
        float f = 0.f;
        if (j < i_r){
          float rem = 1.f - cpj.y*invE;
          float dist = fastsqrt(fmaxf(rem*(float)(i_r-j),0.f));
          float eff = fmaxf(__expf(-g*dist), 1e-5f);
          f = __expf(cpj.x*eff - m2p);
        }
        sv[c][jj]=f; fs+=f; fm=fmaxf(fm,f);
        float4 v0 = *(const float4*)&vrow[j][0];
        float4 v1 = *(const float4*)&vrow[j][4];
        float4 v2 = *(const float4*)&vrow[j][8];
        float4 v3 = *(const float4*)&vrow[j][12];
        acc[0]+=f*v0.x;  acc[1]+=f*v0.y;  acc[2]+=f*v0.z;  acc[3]+=f*v0.w;
        acc[4]+=f*v1.x;  acc[5]+=f*v1.y;  acc[6]+=f*v1.z;  acc[7]+=f*v1.w;
        acc[8]+=f*v2.x;  acc[9]+=f*v2.y;  acc[10]+=f*v2.z; acc[11]+=f*v2.w;
        acc[12]+=f*v3.x; acc[13]+=f*v3.y; acc[14]+=f*v3.z; acc[15]+=f*v3.w;
      }
    }
    // reduce fs, fm over the 16 lanes of this row half
#pragma unroll
    for(int o=8;o>0;o>>=1){
      fs += __shfl_xor_sync(0xffffffffu, fs, o);
      fm  = fmaxf(fm, __shfl_xor_sync(0xffffffffu, fm, o));
    }
    float fac = (fs>0.f)? fminf(1.f/fm, 5.f/fs) : 0.f;

    float* krow = ks + ksbh + (size_t)i_r*4096;
#pragma unroll
    for(int c=0;c<8;c++){
      if (c > cqg) break;
#pragma unroll
      for(int jj=0;jj<2;jj++)
        krow[32*c + 16*jj + l16] = sv[c][jj]*fac;
    }
    for(int c=cqg+1;c<8;c++)
      *(float2*)&krow[32*c + 2*l16] = make_float2(0.f, 0.f);

    // reduce acc[16] over 16 lanes (split-tree): lane l16 ends with d = l16
    float v8[8];
    {
      float s[16];
#pragma unroll
      for(int d=0;d<16;d++) s[d]=acc[d]+__shfl_xor_sync(0xffffffffu,acc[d],8);
      int hi = l16&8;
#pragma unroll
      for(int k2=0;k2<8;k2++) v8[k2]= hi? s[k2+8]:s[k2];
    }
    float v4r[4];
    {
      float s[8];
#pragma unroll
      for(int k2=0;k2<8;k2++) s[k2]=v8[k2]+__shfl_xor_sync(0xffffffffu,v8[k2],4);
      int hi = l16&4;
#pragma unroll
      for(int k2=0;k2<4;k2++) v4r[k2]= hi? s[k2+4]:s[k2];
    }
    float v2r[2];
    {
      float s[4];
#pragma unroll
      for(int k2=0;k2<4;k2++) s[k2]=v4r[k2]+__shfl_xor_sync(0xffffffffu,v4r[k2],2);
      int hi = l16&2;
#pragma unroll
      for(int k2=0;k2<2;k2++) v2r[k2]= hi? s[k2+2]:s[k2];
    }
    float r0;
    {
      float s0=v2r[0]+__shfl_xor_sync(0xffffffffu,v2r[0],1);
      float s1=v2r[1]+__shfl_xor_sync(0xffffffffu,v2r[1],1);
      r0 = (l16&1)? s1:s0;
    }
    o4[((size_t)(bn*256 + i_r))*128 + h*16 + l16] = r0*fac;
  }
}

// ---- fused: t = A@Wo^T+bo+res ; p = LN(t) ; v4 = p@Wv^T+bv  (tile 16x128) --
__global__ __launch_bounds__(256) void gemm_ln_v4_k(
    const float* __restrict__ A, const float* __restrict__ Wo, const float* __restrict__ bo,
    const float* __restrict__ res, const float* __restrict__ lng, const float* __restrict__ lnb,
    const float* __restrict__ Wv, const float* __restrict__ bv, float* __restrict__ out)
{
  __shared__ __align__(16) float At[16][132];
  __shared__ __align__(16) float Ws[16][132];
  int bm = blockIdx.x*16;
  int t = threadIdx.x;
  int tx = t & 31, ty = t >> 5;
#pragma unroll
  for(int i=0;i<8;i++){ int e=t+i*256; int m=e>>7, k=e&127; At[m][k]=A[(size_t)(bm+m)*128+k]; }
  __syncthreads();

  float acc[2][4];
#pragma unroll
  for(int i=0;i<2;i++)
#pragma unroll
    for(int j=0;j<4;j++) acc[i][j]=0.f;
  for(int k0=0;k0<128;k0+=16){
#pragma unroll
    for(int i=0;i<8;i++){ int e=t+i*256; int kk=e&15, n=e>>4; Ws[kk][n]=Wo[(size_t)n*128+k0+kk]; }
    __syncthreads();
#pragma unroll
    for(int kk=0;kk<16;kk++){
      float a0=At[2*ty][k0+kk], a1=At[2*ty+1][k0+kk];
      float4 bq=*(const float4*)&Ws[kk][4*tx];
      acc[0][0]+=a0*bq.x; acc[0][1]+=a0*bq.y; acc[0][2]+=a0*bq.z; acc[0][3]+=a0*bq.w;
      acc[1][0]+=a1*bq.x; acc[1][1]+=a1*bq.y; acc[1][2]+=a1*bq.z; acc[1][3]+=a1*bq.w;
    }
    __syncthreads();
  }
  {
    float4 bb=*(const float4*)&bo[4*tx];
#pragma unroll
    for(int i=0;i<2;i++){
      int m = 2*ty+i;
      float4 rr=*(const float4*)&res[(size_t)(bm+m)*128+4*tx];
      At[m][4*tx+0]=acc[i][0]+bb.x+rr.x;
      At[m][4*tx+1]=acc[i][1]+bb.y+rr.y;
      At[m][4*tx+2]=acc[i][2]+bb.z+rr.z;
      At[m][4*tx+3]=acc[i][3]+bb.w+rr.w;
    }
  }
  __syncthreads();
#pragma unroll
  for(int rr=0; rr<2; rr++){
    int m = 2*ty + rr;
    float x[4];
#pragma unroll
    for(int u=0;u<4;u++) x[u]=At[m][tx+32*u];
    float s = warpSum(x[0]+x[1]+x[2]+x[3]);
    float mean = s*(1.f/128.f);
    float vsum = 0.f;
#pragma unroll
    for(int u=0;u<4;u++){ float d=x[u]-mean; vsum += d*d; }
    vsum = warpSum(vsum);
    float rstd = rsqrtf(vsum*(1.f/128.f)+1e-5f);
#pragma unroll
    for(int u=0;u<4;u++){
      int cix = tx+32*u;
      At[m][cix] = (x[u]-mean)*rstd*lng[cix]+lnb[cix];
    }
  }
  __syncthreads();
#pragma unroll
  for(int i=0;i<2;i++)
#pragma unroll
    for(int j=0;j<4;j++) acc[i][j]=0.f;
  for(int k0=0;k0<128;k0+=16){
#pragma unroll
    for(int i=0;i<8;i++){ int e=t+i*256; int kk=e&15, n=e>>4; Ws[kk][n]=Wv[(size_t)n*128+k0+kk]; }
    __syncthreads();
#pragma unroll
    for(int kk=0;kk<16;kk++){
      float a0=At[2*ty][k0+kk], a1=At[2*ty+1][k0+kk];
      float4 bq=*(const float4*)&Ws[kk][4*tx];
      acc[0][0]+=a0*bq.x; acc[0][1]+=a0*bq.y; acc[0][2]+=a0*bq.z; acc[0][3]+=a0*bq.w;
      acc[1][0]+=a1*bq.x; acc[1][1]+=a1*bq.y; acc[1][2]+=a1*bq.z; acc[1][3]+=a1*bq.w;
    }
    __syncthreads();
  }
  {
    float4 bb=*(const float4*)&bv[4*tx];
#pragma unroll
    for(int i=0;i<2;i++){
      int m = bm + 2*ty + i;
      float4 o; o.x=acc[i][0]+bb.x; o.y=acc[i][1]+bb.y; o.z=acc[i][2]+bb.z; o.w=acc[i][3]+bb.w;
      *(float4*)&out[(size_t)m*128 + 4*tx] = o;
    }
  }
}

// ---- fused: t = A@Wo^T+bo+know ; z = LN(t) permuted-store (tile 32x128) ---
// 32-row tiles: W smem traffic + sync count per output row halved vs 16-row.
// nk and b are constant per block (32 | 256).
__global__ __launch_bounds__(256) void gemm_ln_z_k(
    const float* __restrict__ A, const float* __restrict__ Wo, const float* __restrict__ bo,
    const float* __restrict__ know, const float* __restrict__ lng, const float* __restrict__ lnb,
    float* __restrict__ zout)
{
  __shared__ __align__(16) float At[32][132];
  __shared__ __align__(16) float Ws[16][132];
  int bm = blockIdx.x*32;                 // row = (b*16+nk)*256 + i
  int t = threadIdx.x;
  int tx = t & 31, ty = t >> 5;           // cols 4tx.., rows 4ty..4ty+3
  int bconst = bm >> 12;
  int nkconst = (bm >> 8) & 15;

#pragma unroll
  for(int i=0;i<16;i++){ int e=t+i*256; int m=e>>7, k=e&127; At[m][k]=A[(size_t)(bm+m)*128+k]; }
  __syncthreads();

  float acc[4][4];
#pragma unroll
  for(int i=0;i<4;i++)
#pragma unroll
    for(int j=0;j<4;j++) acc[i][j]=0.f;
  for(int k0=0;k0<128;k0+=16){
#pragma unroll
    for(int i=0;i<8;i++){ int e=t+i*256; int kk=e&15, n=e>>4; Ws[kk][n]=Wo[(size_t)n*128+k0+kk]; }
    __syncthreads();
#pragma unroll
    for(int kk=0;kk<16;kk++){
      float a0=At[4*ty  ][k0+kk];
      float a1=At[4*ty+1][k0+kk];
      float a2=At[4*ty+2][k0+kk];
      float a3=At[4*ty+3][k0+kk];
      float4 bq=*(const float4*)&Ws[kk][4*tx];
      acc[0][0]+=a0*bq.x; acc[0][1]+=a0*bq.y; acc[0][2]+=a0*bq.z; acc[0][3]+=a0*bq.w;
      acc[1][0]+=a1*bq.x; acc[1][1]+=a1*bq.y; acc[1][2]+=a1*bq.z; acc[1][3]+=a1*bq.w;
      acc[2][0]+=a2*bq.x; acc[2][1]+=a2*bq.y; acc[2][2]+=a2*bq.z; acc[2][3]+=a2*bq.w;
      acc[3][0]+=a3*bq.x; acc[3][1]+=a3*bq.y; acc[3][2]+=a3*bq.z; acc[3][3]+=a3*bq.w;
    }
    __syncthreads();
  }
  {
    float4 bb=*(const float4*)&bo[4*tx];
    float4 kn=*(const float4*)&know[(size_t)nkconst*128+4*tx];
#pragma unroll
    for(int i=0;i<4;i++){
      int m = 4*ty+i;
      At[m][4*tx+0]=acc[i][0]+bb.x+kn.x;
      At[m][4*tx+1]=acc[i][1]+bb.y+kn.y;
      At[m][4*tx+2]=acc[i][2]+bb.z+kn.z;
      At[m][4*tx+3]=acc[i][3]+bb.w+kn.w;
    }
  }
  __syncthreads();
#pragma unroll
  for(int rr=0; rr<4; rr++){
    int m = 4*ty + rr;
    int i = (bm + m) & 255;
    size_t zbase = (((size_t)(bconst*256+i))*16 + nkconst)*128;
    float x[4];
#pragma unroll
    for(int u=0;u<4;u++) x[u]=At[m][tx+32*u];
    float s = warpSum(x[0]+x[1]+x[2]+x[3]);
    float mean = s*(1.f/128.f);
    float vsum = 0.f;
#pragma unroll
    for(int u=0;u<4;u++){ float d=x[u]-mean; vsum += d*d; }
    vsum = warpSum(vsum);
    float rstd = rsqrtf(vsum*(1.f/128.f)+1e-5f);
#pragma unroll
    for(int u=0;u<4;u++){
      int cix = tx+32*u;
      zout[zbase + cix] = (x[u]-mean)*rstd*lng[cix]+lnb[cix];
    }
  }
}

// ---------------- launch ----------------
extern "C" void kernel_launch(void* const* d_in, const int* in_sizes, int n_in,
                              void* d_out, int out_size)
{
  const float* q_emb   = (const float*)d_in[0];
  const float* s_emb   = (const float*)d_in[1];
  const float* b1_Wq   = (const float*)d_in[3];
  const float* b1_bq   = (const float*)d_in[4];
  const float* b1_Wv   = (const float*)d_in[5];
  const float* b1_bv   = (const float*)d_in[6];
  const float* b1_Wo   = (const float*)d_in[7];
  const float* b1_bo   = (const float*)d_in[8];
  const float* b1_ga   = (const float*)d_in[9];
  const float* b1_lng  = (const float*)d_in[10];
  const float* b1_lnb  = (const float*)d_in[11];
  const float* b4_Wq   = (const float*)d_in[12];
  const float* b4_bq   = (const float*)d_in[13];
  const float* b4_Wk   = (const float*)d_in[14];
  const float* b4_bk   = (const float*)d_in[15];
  const float* b4_Wv   = (const float*)d_in[16];
  const float* b4_bv   = (const float*)d_in[17];
  const float* b4_Wo   = (const float*)d_in[18];
  const float* b4_bo   = (const float*)d_in[19];
  const float* b4_ga   = (const float*)d_in[20];
  const float* b4_lng  = (const float*)d_in[21];
  const float* b4_lnb  = (const float*)d_in[22];
  const float* know    = (const float*)d_in[23];

  float* out  = (float*)d_out;
  float* zout = out;                 // z:        4*256*16*128 = 2097152
  float* qs   = out + 2097152;       // q_scores: 4*8*256*256  = 2097152
  float* ks   = out + 4194304;       // k_scores: 4*8*256*16*256 = 33554432

  float *p_q1,*p_v1,*p_o1,*p_k4,*p_v4,*p_q4,*p_o4;
  cudaGetSymbolAddress((void**)&p_q1, g_q1);
  cudaGetSymbolAddress((void**)&p_v1, g_v1);
  cudaGetSymbolAddress((void**)&p_o1, g_o1);
  cudaGetSymbolAddress((void**)&p_k4, g_k4);
  cudaGetSymbolAddress((void**)&p_v4, g_v4);
  cudaGetSymbolAddress((void**)&p_q4, g_q4);
  cudaGetSymbolAddress((void**)&p_o4, g_o4);

  // 1) all independent projections in one launch
  proj4<<<dim3(32,2,4),256>>>(
      q_emb, b1_Wq, b1_bq, p_q1, 1024,
      s_emb, b1_Wv, b1_bv, p_v1, 1024,
      q_emb, b4_Wk, b4_bk, p_k4, 1024,
      know,  b4_Wq, b4_bq, p_q4, 16);

  // 2) block1 attention
  attn1_kernel<<<dim3(32,4),256>>>(p_q1, p_v1, b1_ga, qs, p_o1);

  // 3) o1@Wo1 + q_emb residual -> LN -> @Wv4 -> v4 (p never materialized)
  gemm_ln_v4_k<<<64,256>>>(p_o1, b1_Wo, b1_bo, q_emb, b1_lng, b1_lnb,
                           b4_Wv, b4_bv, p_v4);

  // 4) block4 attention
  attn4_kernel<<<dim3(512,2),256>>>(p_q4, p_k4, p_v4, b4_ga, ks, p_o4);

  // 5) o4@Wo4 + know residual -> LN -> permuted z (32-row tiles)
  gemm_ln_z_k<<<512,256>>>(p_o4, b4_Wo, b4_bo, know, b4_lng, b4_lnb, zout);
}

// round 15
// speedup vs baseline: 1.2009x; 1.0817x over previous
#include <cuda_runtime.h>
#include <math.h>

#define DM 128
#define NH 8
#define NKN 16
#define BSZ 4
#define SEQ 256
#define DK 16

// ---------------- scratch (no allocations allowed) ----------------
__device__ float g_q1[BSZ*SEQ*DM];
__device__ float g_v1[BSZ*SEQ*DM];
__device__ float g_o1[BSZ*SEQ*DM];
__device__ float g_k4[BSZ*SEQ*DM];
__device__ float g_v4[BSZ*SEQ*DM];
__device__ float g_q4[NKN*DM];
__device__ float g_o4[BSZ*NKN*SEQ*DM];

__device__ __forceinline__ float warpMax(float v){
#pragma unroll
  for(int o=16;o>0;o>>=1) v = fmaxf(v, __shfl_xor_sync(0xffffffffu, v, o));
  return v;
}
__device__ __forceinline__ float warpSum(float v){
#pragma unroll
  for(int o=16;o>0;o>>=1) v += __shfl_xor_sync(0xffffffffu, v, o);
  return v;
}
__device__ __forceinline__ float fastsqrt(float x){
  float r; asm("sqrt.approx.f32 %0, %1;" : "=f"(r) : "f"(x)); return r;
}
// Reduce acc[16] across 32 lanes with 31 shfl; result: lane l holds sum for d = l>>1.
__device__ __forceinline__ float reduce16x32(const float* acc, int lane){
  float v[8];
  {
    float s[16];
#pragma unroll
    for(int d=0;d<16;d++) s[d]=acc[d]+__shfl_xor_sync(0xffffffffu,acc[d],16);
    int hi = lane&16;
#pragma unroll
    for(int k=0;k<8;k++) v[k]= hi? s[k+8]:s[k];
  }
  {
    float s[8];
#pragma unroll
    for(int k=0;k<8;k++) s[k]=v[k]+__shfl_xor_sync(0xffffffffu,v[k],8);
    int hi = lane&8;
#pragma unroll
    for(int k=0;k<4;k++) v[k]= hi? s[k+4]:s[k];
  }
  {
    float s[4];
#pragma unroll
    for(int k=0;k<4;k++) s[k]=v[k]+__shfl_xor_sync(0xffffffffu,v[k],4);
    int hi = lane&4;
#pragma unroll
    for(int k=0;k<2;k++) v[k]= hi? s[k+2]:s[k];
  }
  {
    float s0=v[0]+__shfl_xor_sync(0xffffffffu,v[0],2);
    float s1=v[1]+__shfl_xor_sync(0xffffffffu,v[1],2);
    v[0] = (lane&2)? s1:s0;
  }
  v[0]+=__shfl_xor_sync(0xffffffffu,v[0],1);
  return v[0];
}

// ------------- fused 4-way projection: C[M,128] = A@W^T + b (tile 32x64) ---
__global__ __launch_bounds__(256) void proj4(
    const float* __restrict__ A0, const float* __restrict__ W0, const float* __restrict__ B0, float* __restrict__ C0, int M0,
    const float* __restrict__ A1, const float* __restrict__ W1, const float* __restrict__ B1, float* __restrict__ C1, int M1,
    const float* __restrict__ A2, const float* __restrict__ W2, const float* __restrict__ B2, float* __restrict__ C2, int M2,
    const float* __restrict__ A3, const float* __restrict__ W3, const float* __restrict__ B3, float* __restrict__ C3, int M3)
{
  __shared__ __align__(16) float As[16][36];
  __shared__ __align__(16) float Ws[16][68];
  const float *A,*W,*Bv; float* C; int M;
  switch(blockIdx.z){
    case 0: A=A0;W=W0;Bv=B0;C=C0;M=M0; break;
    case 1: A=A1;W=W1;Bv=B1;C=C1;M=M1; break;
    case 2: A=A2;W=W2;Bv=B2;C=C2;M=M2; break;
    default:A=A3;W=W3;Bv=B3;C=C3;M=M3; break;
  }
  int bm = blockIdx.x*32;
  if (bm >= M) return;
  int bn = blockIdx.y*64;
  int t = threadIdx.x;
  int tx = t & 15, ty = t >> 4;
  float acc[2][4];
#pragma unroll
  for(int i=0;i<2;i++)
#pragma unroll
    for(int j=0;j<4;j++) acc[i][j]=0.f;

  for(int k0=0;k0<128;k0+=16){
    {
      int e=t*2; int m=e>>4, kk=e&15;
      As[kk][m]   = (bm+m<M) ? A[(size_t)(bm+m)*128 + k0+kk]   : 0.f;
      As[kk+1][m] = (bm+m<M) ? A[(size_t)(bm+m)*128 + k0+kk+1] : 0.f;
    }
#pragma unroll
    for(int i=0;i<4;i++){
      int e=t+i*256; int m=e>>4, kk=e&15;
      Ws[kk][m] = W[(size_t)(bn+m)*128 + k0+kk];
    }
    __syncthreads();
#pragma unroll
    for(int kk=0;kk<16;kk++){
      float a0=As[kk][2*ty], a1=As[kk][2*ty+1];
      float4 b=*(const float4*)&Ws[kk][4*tx];
      acc[0][0]+=a0*b.x; acc[0][1]+=a0*b.y; acc[0][2]+=a0*b.z; acc[0][3]+=a0*b.w;
      acc[1][0]+=a1*b.x; acc[1][1]+=a1*b.y; acc[1][2]+=a1*b.z; acc[1][3]+=a1*b.w;
    }
    __syncthreads();
  }
  float4 bb = *(const float4*)&Bv[bn+4*tx];
#pragma unroll
  for(int i=0;i<2;i++){
    int m = bm + 2*ty + i;
    if (m < M){
      float4 o; o.x=acc[i][0]+bb.x; o.y=acc[i][1]+bb.y; o.z=acc[i][2]+bb.z; o.w=acc[i][3]+bb.w;
      *(float4*)&C[(size_t)m*128 + bn + 4*tx] = o;
    }
  }
}

// ---------------- block1 attention (K == Q, j<=i, no maxout) ---------------
// grid (32, 8): 32-row groups -> 256 blocks (fills 148 SMs)
__global__ __launch_bounds__(256) void attn1_kernel(
    const float* __restrict__ q1, const float* __restrict__ v1,
    const float* __restrict__ gamma, float* __restrict__ qs,
    float* __restrict__ o1)
{
  __shared__ float kq[16][256];
  __shared__ float vt[16][256];
  int bh = blockIdx.x;
  int rg = blockIdx.y;            // 0..7
  int b = bh >> 3, h = bh & 7;
  int t = threadIdx.x;
  for(int e=t; e<4096; e+=256){
    int j = e>>4, d = e&15;
    size_t src = ((size_t)(b*256+j))*128 + h*16 + d;
    kq[d][j] = q1[src];
    vt[d][j] = v1[src];
  }
  __syncthreads();
  int w = t>>5, lane = t&31;
  float g = fabsf(gamma[h]);

  for(int r=0;r<4;r++){
    int i = rg*32 + w + 8*r;
    int cq = i>>5;
    float qv[16];
#pragma unroll
    for(int d=0;d<16;d++) qv[d]=kq[d][i];

    float rawv[8], Pv[8];
    float m1 = -1e30f;
#pragma unroll
    for(int c=0;c<8;c++){
      if (c > cq) break;
      int j = 32*c + lane;
      float s = 0.f;
      if (j <= i){
#pragma unroll
        for(int d=0;d<16;d++) s += qv[d]*kq[d][j];
        s *= 0.25f;
        m1 = fmaxf(m1, s);
      }
      rawv[c] = s;
    }
    m1 = warpMax(m1);

    float run = 0.f;
#pragma unroll
    for(int c=0;c<8;c++){
      if (c > cq) break;
      int j = 32*c + lane;
      float e = (j<=i) ? __expf(rawv[c]-m1) : 0.f;
      float x = e;
#pragma unroll
      for(int o=1;o<32;o<<=1){ float y=__shfl_up_sync(0xffffffffu,x,o); if (lane>=o) x += y; }
      Pv[c] = run + x;
      run  += __shfl_sync(0xffffffffu, x, 31);
    }
    float invE = 1.f/run;
    float m2p = fmaxf(m1, 0.f);

    float fs = 0.f;
#pragma unroll
    for(int c=0;c<8;c++){
      if (c > cq) break;
      int j = 32*c + lane;
      float f = 0.f;
      if (j<=i){
        float rem1 = 1.f - Pv[c]*invE;
        float dist = fastsqrt(fmaxf(rem1*(float)(i-j), 0.f));
        float eff = fmaxf(__expf(-g*dist), 1e-5f);
        f = __expf(rawv[c]*eff - m2p);
      }
      rawv[c] = f;
      fs += f;
    }
    fs = warpSum(fs);
    float inv = 1.f/fs;

    float acc[16];
#pragma unroll
    for(int d=0;d<16;d++) acc[d]=0.f;
    size_t qbase = ((size_t)bh*256 + i)*256;
#pragma unroll
    for(int c=0;c<8;c++){
      if (c > cq) break;
      int j = 32*c + lane;
      float pf = rawv[c]*inv;
      qs[qbase + j] = pf;
#pragma unroll
      for(int d=0;d<16;d++) acc[d] += pf*vt[d][j];
    }
    for(int c=cq+1;c<8;c++) qs[qbase + 32*c + lane] = 0.f;

    float red = reduce16x32(acc, lane);
    if (!(lane&1)){
      size_t ob = ((size_t)(b*256 + i))*128 + h*16;
      o1[ob + (lane>>1)] = red;
    }
  }
}

// ---------------- block4 attention v2.5: 2 rows per warp-pass --------------
// (measured-best 2-row config: 64 regs, 4 blocks/SM)
__global__ __launch_bounds__(256) void attn4_kernel(
    const float* __restrict__ q4, const float* __restrict__ k4,
    const float* __restrict__ v4, const float* __restrict__ gamma,
    float* __restrict__ ks, float* __restrict__ o4)
{
  __shared__ __align__(16) float vrow[256][20];   // K rows, then V rows
  __shared__ __align__(8)  float2 cp[256];        // (c_j, P_j)
  __shared__ float qv_sh[16];
  __shared__ float m2c_sh;
  int bid = blockIdx.x;           // (b*NKN+nk)*NH + h
  int rg = blockIdx.y;            // 0..1
  int h = bid & 7;
  int bn = bid >> 3;              // b*NKN + nk
  int b = bn >> 4, nk = bn & 15;
  int t = threadIdx.x;

  if (t < 16) qv_sh[t] = q4[nk*128 + h*16 + t];
  const float* kg = k4 + (size_t)b*256*128 + h*16;
#pragma unroll
  for(int it=0; it<4; it++){
    int e = t + it*256;
    int j = e >> 2, d4 = (e & 3)*4;
    *(float4*)&vrow[j][d4] = *(const float4*)(kg + (size_t)j*128 + d4);
  }
  __syncthreads();
  {
    float s = 0.f;
#pragma unroll
    for(int u=0;u<4;u++){
      float4 kk4 = *(const float4*)&vrow[t][4*u];
      s += qv_sh[4*u]*kk4.x + qv_sh[4*u+1]*kk4.y + qv_sh[4*u+2]*kk4.z + qv_sh[4*u+3]*kk4.w;
    }
    cp[t].x = s*0.25f;
  }
  __syncthreads();
  // all threads overwrite vrow with V; warp0 additionally does max + prefix scan
  const float* vg = v4 + (size_t)b*256*128 + h*16;
#pragma unroll
  for(int it=0; it<4; it++){
    int e = t + it*256;
    int j = e >> 2, d4 = (e & 3)*4;
    *(float4*)&vrow[j][d4] = *(const float4*)(vg + (size_t)j*128 + d4);
  }
  if (t < 32){
    float m = -1e30f;
#pragma unroll
    for(int q=0;q<8;q++) m = fmaxf(m, cp[t + 32*q].x);
    m = warpMax(m);
    float loc[8]; float run = 0.f;
#pragma unroll
    for(int c=0;c<8;c++){ loc[c] = __expf(cp[t*8+c].x - m); run += loc[c]; }
    float incl = run;
#pragma unroll
    for(int o=1;o<32;o<<=1){ float y=__shfl_up_sync(0xffffffffu,incl,o); if (t>=o) incl += y; }
    float base = incl - run;
#pragma unroll
    for(int c=0;c<8;c++){ base += loc[c]; cp[t*8+c].y = base; }
    if (t==0) m2c_sh = fmaxf(m, 0.f);
  }
  __syncthreads();

  int w = t>>5, lane = t&31;
  int rr = lane>>4, l16 = lane&15;
  float g = fabsf(gamma[h]);
  float m2p = m2c_sh;
  size_t ksbh = (((size_t)(b*8 + h))*256)*4096 + (size_t)nk*256;

  for(int p=0;p<8;p++){
    int i0 = rg*128 + 2*(w + 8*p);
    int i_r = i0 + rr;                 // this half-warp's row
    int cqg = i0 >> 5;                 // max needed chunk for the pair
    int pidx = (i_r>0)? i_r-1 : 0;
    float invE = 1.f/cp[pidx].y;

    float sv[8][2];
    float acc[16];
    float fs=0.f, fm=0.f;
#pragma unroll
    for(int d=0;d<16;d++) acc[d]=0.f;

#pragma unroll
    for(int c=0;c<8;c++){
      if (c > cqg) break;
#pragma unroll
      for(int jj=0;jj<2;jj++){
        int j = 32*c + 16*jj + l16;
        float2 cpj = cp[j];
        float f = 0.f;
        if (j < i_r){
          float rem = 1.f - cpj.y*invE;
          float dist = fastsqrt(fmaxf(rem*(float)(i_r-j),0.f));
          float eff = fmaxf(__expf(-g*dist), 1e-5f);
          f = __expf(cpj.x*eff - m2p);
        }
        sv[c][jj]=f; fs+=f; fm=fmaxf(fm,f);
        float4 v0 = *(const float4*)&vrow[j][0];
        float4 v1 = *(const float4*)&vrow[j][4];
        float4 v2 = *(const float4*)&vrow[j][8];
        float4 v3 = *(const float4*)&vrow[j][12];
        acc[0]+=f*v0.x;  acc[1]+=f*v0.y;  acc[2]+=f*v0.z;  acc[3]+=f*v0.w;
        acc[4]+=f*v1.x;  acc[5]+=f*v1.y;  acc[6]+=f*v1.z;  acc[7]+=f*v1.w;
        acc[8]+=f*v2.x;  acc[9]+=f*v2.y;  acc[10]+=f*v2.z; acc[11]+=f*v2.w;
        acc[12]+=f*v3.x; acc[13]+=f*v3.y; acc[14]+=f*v3.z; acc[15]+=f*v3.w;
      }
    }
    // reduce fs, fm over the 16 lanes of this row half
#pragma unroll
    for(int o=8;o>0;o>>=1){
      fs += __shfl_xor_sync(0xffffffffu, fs, o);
      fm  = fmaxf(fm, __shfl_xor_sync(0xffffffffu, fm, o));
    }
    float fac = (fs>0.f)? fminf(1.f/fm, 5.f/fs) : 0.f;

    float* krow = ks + ksbh + (size_t)i_r*4096;
#pragma unroll
    for(int c=0;c<8;c++){
      if (c > cqg) break;
#pragma unroll
      for(int jj=0;jj<2;jj++)
        krow[32*c + 16*jj + l16] = sv[c][jj]*fac;
    }
    for(int c=cqg+1;c<8;c++)
      *(float2*)&krow[32*c + 2*l16] = make_float2(0.f, 0.f);

    // reduce acc[16] over 16 lanes (split-tree): lane l16 ends with d = l16
    float v8[8];
    {
      float s[16];
#pragma unroll
      for(int d=0;d<16;d++) s[d]=acc[d]+__shfl_xor_sync(0xffffffffu,acc[d],8);
      int hi = l16&8;
#pragma unroll
      for(int k2=0;k2<8;k2++) v8[k2]= hi? s[k2+8]:s[k2];
    }
    float v4r[4];
    {
      float s[8];
#pragma unroll
      for(int k2=0;k2<8;k2++) s[k2]=v8[k2]+__shfl_xor_sync(0xffffffffu,v8[k2],4);
      int hi = l16&4;
#pragma unroll
      for(int k2=0;k2<4;k2++) v4r[k2]= hi? s[k2+4]:s[k2];
    }
    float v2r[2];
    {
      float s[4];
#pragma unroll
      for(int k2=0;k2<4;k2++) s[k2]=v4r[k2]+__shfl_xor_sync(0xffffffffu,v4r[k2],2);
      int hi = l16&2;
#pragma unroll
      for(int k2=0;k2<2;k2++) v2r[k2]= hi? s[k2+2]:s[k2];
    }
    float r0;
    {
      float s0=v2r[0]+__shfl_xor_sync(0xffffffffu,v2r[0],1);
      float s1=v2r[1]+__shfl_xor_sync(0xffffffffu,v2r[1],1);
      r0 = (l16&1)? s1:s0;
    }
    o4[((size_t)(bn*256 + i_r))*128 + h*16 + l16] = r0*fac;
  }
}

// ---- fused: t = A@Wo^T+bo+res ; p = LN(t) ; v4 = p@Wv^T+bv  (tile 8x128) --
// One warp per row: LN + inter-GEMM staging are warp-local (no block syncs
// beyond the Ws tile loads). grid 128 for full-chip fill.
__global__ __launch_bounds__(256) void gemm_ln_v4_k(
    const float* __restrict__ A, const float* __restrict__ Wo, const float* __restrict__ bo,
    const float* __restrict__ res, const float* __restrict__ lng, const float* __restrict__ lnb,
    const float* __restrict__ Wv, const float* __restrict__ bv, float* __restrict__ out)
{
  __shared__ __align__(16) float At[8][132];
  __shared__ __align__(16) float Ws[16][132];
  int bm = blockIdx.x*8;
  int t = threadIdx.x;
  int tx = t & 31, ty = t >> 5;           // warp ty owns row ty; cols 4tx..
#pragma unroll
  for(int i=0;i<4;i++){ int e=t+i*256; int m=e>>7, k=e&127; At[m][k]=A[(size_t)(bm+m)*128+k]; }
  __syncthreads();

  float acc[4];
#pragma unroll
  for(int j=0;j<4;j++) acc[j]=0.f;
  for(int k0=0;k0<128;k0+=16){
#pragma unroll
    for(int i=0;i<8;i++){ int e=t+i*256; int kk=e&15, n=e>>4; Ws[kk][n]=Wo[(size_t)n*128+k0+kk]; }
    __syncthreads();
#pragma unroll
    for(int kk=0;kk<16;kk++){
      float a0=At[ty][k0+kk];
      float4 bq=*(const float4*)&Ws[kk][4*tx];
      acc[0]+=a0*bq.x; acc[1]+=a0*bq.y; acc[2]+=a0*bq.z; acc[3]+=a0*bq.w;
    }
    __syncthreads();
  }
  {
    float4 bb=*(const float4*)&bo[4*tx];
    float4 rr=*(const float4*)&res[(size_t)(bm+ty)*128+4*tx];
    At[ty][4*tx+0]=acc[0]+bb.x+rr.x;
    At[ty][4*tx+1]=acc[1]+bb.y+rr.y;
    At[ty][4*tx+2]=acc[2]+bb.z+rr.z;
    At[ty][4*tx+3]=acc[3]+bb.w+rr.w;
  }
  __syncwarp();
  // LN on own row (warp-local)
  {
    float x[4];
#pragma unroll
    for(int u=0;u<4;u++) x[u]=At[ty][tx+32*u];
    float s = warpSum(x[0]+x[1]+x[2]+x[3]);
    float mean = s*(1.f/128.f);
    float vsum = 0.f;
#pragma unroll
    for(int u=0;u<4;u++){ float d=x[u]-mean; vsum += d*d; }
    vsum = warpSum(vsum);
    float rstd = rsqrtf(vsum*(1.f/128.f)+1e-5f);
#pragma unroll
    for(int u=0;u<4;u++){
      int cix = tx+32*u;
      At[ty][cix] = (x[u]-mean)*rstd*lng[cix]+lnb[cix];
    }
  }
  __syncwarp();
  // second GEMM: out = At @ Wv^T + bv
#pragma unroll
  for(int j=0;j<4;j++) acc[j]=0.f;
  for(int k0=0;k0<128;k0+=16){
    __syncthreads();
#pragma unroll
    for(int i=0;i<8;i++){ int e=t+i*256; int kk=e&15, n=e>>4; Ws[kk][n]=Wv[(size_t)n*128+k0+kk]; }
    __syncthreads();
#pragma unroll
    for(int kk=0;kk<16;kk++){
      float a0=At[ty][k0+kk];
      float4 bq=*(const float4*)&Ws[kk][4*tx];
      acc[0]+=a0*bq.x; acc[1]+=a0*bq.y; acc[2]+=a0*bq.z; acc[3]+=a0*bq.w;
    }
  }
  {
    float4 bb=*(const float4*)&bv[4*tx];
    float4 o; o.x=acc[0]+bb.x; o.y=acc[1]+bb.y; o.z=acc[2]+bb.z; o.w=acc[3]+bb.w;
    *(float4*)&out[(size_t)(bm+ty)*128 + 4*tx] = o;
  }
}

// ---- fused: t = A@Wo^T+bo+know ; z = LN(t) permuted-store (tile 32x128) ---
__global__ __launch_bounds__(256) void gemm_ln_z_k(
    const float* __restrict__ A, const float* __restrict__ Wo, const float* __restrict__ bo,
    const float* __restrict__ know, const float* __restrict__ lng, const float* __restrict__ lnb,
    float* __restrict__ zout)
{
  __shared__ __align__(16) float At[32][132];
  __shared__ __align__(16) float Ws[16][132];
  int bm = blockIdx.x*32;                 // row = (b*16+nk)*256 + i
  int t = threadIdx.x;
  int tx = t & 31, ty = t >> 5;           // cols 4tx.., rows 4ty..4ty+3
  int bconst = bm >> 12;
  int nkconst = (bm >> 8) & 15;

#pragma unroll
  for(int i=0;i<16;i++){ int e=t+i*256; int m=e>>7, k=e&127; At[m][k]=A[(size_t)(bm+m)*128+k]; }
  __syncthreads();

  float acc[4][4];
#pragma unroll
  for(int i=0;i<4;i++)
#pragma unroll
    for(int j=0;j<4;j++) acc[i][j]=0.f;
  for(int k0=0;k0<128;k0+=16){
#pragma unroll
    for(int i=0;i<8;i++){ int e=t+i*256; int kk=e&15, n=e>>4; Ws[kk][n]=Wo[(size_t)n*128+k0+kk]; }
    __syncthreads();
#pragma unroll
    for(int kk=0;kk<16;kk++){
      float a0=At[4*ty  ][k0+kk];
      float a1=At[4*ty+1][k0+kk];
      float a2=At[4*ty+2][k0+kk];
      float a3=At[4*ty+3][k0+kk];
      float4 bq=*(const float4*)&Ws[kk][4*tx];
      acc[0][0]+=a0*bq.x; acc[0][1]+=a0*bq.y; acc[0][2]+=a0*bq.z; acc[0][3]+=a0*bq.w;
      acc[1][0]+=a1*bq.x; acc[1][1]+=a1*bq.y; acc[1][2]+=a1*bq.z; acc[1][3]+=a1*bq.w;
      acc[2][0]+=a2*bq.x; acc[2][1]+=a2*bq.y; acc[2][2]+=a2*bq.z; acc[2][3]+=a2*bq.w;
      acc[3][0]+=a3*bq.x; acc[3][1]+=a3*bq.y; acc[3][2]+=a3*bq.z; acc[3][3]+=a3*bq.w;
    }
    __syncthreads();
  }
  {
    float4 bb=*(const float4*)&bo[4*tx];
    float4 kn=*(const float4*)&know[(size_t)nkconst*128+4*tx];
#pragma unroll
    for(int i=0;i<4;i++){
      int m = 4*ty+i;
      At[m][4*tx+0]=acc[i][0]+bb.x+kn.x;
      At[m][4*tx+1]=acc[i][1]+bb.y+kn.y;
      At[m][4*tx+2]=acc[i][2]+bb.z+kn.z;
      At[m][4*tx+3]=acc[i][3]+bb.w+kn.w;
    }
  }
  __syncthreads();
#pragma unroll
  for(int rr=0; rr<4; rr++){
    int m = 4*ty + rr;
    int i = (bm + m) & 255;
    size_t zbase = (((size_t)(bconst*256+i))*16 + nkconst)*128;
    float x[4];
#pragma unroll
    for(int u=0;u<4;u++) x[u]=At[m][tx+32*u];
    float s = warpSum(x[0]+x[1]+x[2]+x[3]);
    float mean = s*(1.f/128.f);
    float vsum = 0.f;
#pragma unroll
    for(int u=0;u<4;u++){ float d=x[u]-mean; vsum += d*d; }
    vsum = warpSum(vsum);
    float rstd = rsqrtf(vsum*(1.f/128.f)+1e-5f);
#pragma unroll
    for(int u=0;u<4;u++){
      int cix = tx+32*u;
      zout[zbase + cix] = (x[u]-mean)*rstd*lng[cix]+lnb[cix];
    }
  }
}

// ---------------- launch ----------------
extern "C" void kernel_launch(void* const* d_in, const int* in_sizes, int n_in,
                              void* d_out, int out_size)
{
  const float* q_emb   = (const float*)d_in[0];
  const float* s_emb   = (const float*)d_in[1];
  const float* b1_Wq   = (const float*)d_in[3];
  const float* b1_bq   = (const float*)d_in[4];
  const float* b1_Wv   = (const float*)d_in[5];
  const float* b1_bv   = (const float*)d_in[6];
  const float* b1_Wo   = (const float*)d_in[7];
  const float* b1_bo   = (const float*)d_in[8];
  const float* b1_ga   = (const float*)d_in[9];
  const float* b1_lng  = (const float*)d_in[10];
  const float* b1_lnb  = (const float*)d_in[11];
  const float* b4_Wq   = (const float*)d_in[12];
  const float* b4_bq   = (const float*)d_in[13];
  const float* b4_Wk   = (const float*)d_in[14];
  const float* b4_bk   = (const float*)d_in[15];
  const float* b4_Wv   = (const float*)d_in[16];
  const float* b4_bv   = (const float*)d_in[17];
  const float* b4_Wo   = (const float*)d_in[18];
  const float* b4_bo   = (const float*)d_in[19];
  const float* b4_ga   = (const float*)d_in[20];
  const float* b4_lng  = (const float*)d_in[21];
  const float* b4_lnb  = (const float*)d_in[22];
  const float* know    = (const float*)d_in[23];

  float* out  = (float*)d_out;
  float* zout = out;                 // z:        4*256*16*128 = 2097152
  float* qs   = out + 2097152;       // q_scores: 4*8*256*256  = 2097152
  float* ks   = out + 4194304;       // k_scores: 4*8*256*16*256 = 33554432

  float *p_q1,*p_v1,*p_o1,*p_k4,*p_v4,*p_q4,*p_o4;
  cudaGetSymbolAddress((void**)&p_q1, g_q1);
  cudaGetSymbolAddress((void**)&p_v1, g_v1);
  cudaGetSymbolAddress((void**)&p_o1, g_o1);
  cudaGetSymbolAddress((void**)&p_k4, g_k4);
  cudaGetSymbolAddress((void**)&p_v4, g_v4);
  cudaGetSymbolAddress((void**)&p_q4, g_q4);
  cudaGetSymbolAddress((void**)&p_o4, g_o4);

  // 1) all independent projections in one launch
  proj4<<<dim3(32,2,4),256>>>(
      q_emb, b1_Wq, b1_bq, p_q1, 1024,
      s_emb, b1_Wv, b1_bv, p_v1, 1024,
      q_emb, b4_Wk, b4_bk, p_k4, 1024,
      know,  b4_Wq, b4_bq, p_q4, 16);

  // 2) block1 attention (256 blocks)
  attn1_kernel<<<dim3(32,8),256>>>(p_q1, p_v1, b1_ga, qs, p_o1);

  // 3) o1@Wo1 + q_emb residual -> LN -> @Wv4 -> v4 (8-row tiles, grid 128)
  gemm_ln_v4_k<<<128,256>>>(p_o1, b1_Wo, b1_bo, q_emb, b1_lng, b1_lnb,
                            b4_Wv, b4_bv, p_v4);

  // 4) block4 attention
  attn4_kernel<<<dim3(512,2),256>>>(p_q4, p_k4, p_v4, b4_ga, ks, p_o4);

  // 5) o4@Wo4 + know residual -> LN -> permuted z (32-row tiles)
  gemm_ln_z_k<<<512,256>>>(p_o4, b4_Wo, b4_bo, know, b4_lng, b4_lnb, zout);
}